// round 8
// baseline (speedup 1.0000x reference)
#include <cuda_runtime.h>
#include <cuda_fp16.h>
#include <cstdint>
#include <math.h>

#define T_ 512
#define B_ 64
#define N_ 1024
#define G_ 4096   // 4*N
#define SPH 68    // smem pitch (u32) for fp16 h tiles (128 fp16 = 64 u32 + 4 pad)

// ---------------- static device scratch ----------------
__device__ float g_Pf[(size_t)T_ * B_ * G_];
__device__ float g_Pb[(size_t)T_ * B_ * G_];
__device__ float g_Pc[(size_t)T_ * B_ * G_];
__device__ __half g_bi16[(size_t)T_ * B_ * 2 * N_];   // bilstm output, fp16
__device__ __half g_x16[(size_t)B_ * T_ * N_];        // inputs converted to fp16
__device__ __half g_Wih16[16 * 1024 * 1024];          // fp16 W_ih: f(4M) b(4M) c(8M)
__device__ __half g_h16[6][B_ * N_];                  // fp16 recurrent h
__device__ float  g_c[3][B_ * N_];                    // fp32 cell state
__device__ uint32_t g_Wsw_bi[2 * 64 * 32768];         // fp16 frag-swizzled W_hh fwd/bwd
__device__ uint32_t g_Wsw_c[128 * 16384];             // fp16 frag-swizzled W_hh cell

__device__ unsigned g_barc[2] = {0, 0};
__device__ unsigned g_barg[2] = {0, 0};

__device__ __forceinline__ void grid_barrier(int which, unsigned nb) {
    __syncthreads();
    if (threadIdx.x == 0) {
        __threadfence();
        volatile unsigned* gen = &g_barg[which];
        unsigned g = *gen;
        if (atomicAdd(&g_barc[which], 1) == nb - 1) {
            g_barc[which] = 0;
            __threadfence();
            atomicExch((unsigned*)gen, g + 1);
        } else {
            while (*gen == g) { }
            __threadfence();
        }
    }
    __syncthreads();
}

__global__ void zero_state_kernel() {
    int i = blockIdx.x * blockDim.x + threadIdx.x;
    if (i < 6 * B_ * N_ / 2) ((uint32_t*)g_h16)[i] = 0;
    if (i < 3 * B_ * N_) ((float*)g_c)[i] = 0.0f;
}

// ---------------- mma / cp.async / ldmatrix helpers ----------------
__device__ __forceinline__ void mma_f16(float* c, const uint32_t* a, const uint32_t* b) {
    asm volatile(
        "mma.sync.aligned.m16n8k16.row.col.f32.f16.f16.f32 "
        "{%0,%1,%2,%3}, {%4,%5,%6,%7}, {%8,%9}, {%0,%1,%2,%3};"
        : "+f"(c[0]), "+f"(c[1]), "+f"(c[2]), "+f"(c[3])
        : "r"(a[0]), "r"(a[1]), "r"(a[2]), "r"(a[3]), "r"(b[0]), "r"(b[1]));
}
__device__ __forceinline__ void ldsm_x4(uint32_t& r0, uint32_t& r1, uint32_t& r2, uint32_t& r3,
                                        uint32_t addr) {
    asm volatile("ldmatrix.sync.aligned.m8n8.x4.shared.b16 {%0,%1,%2,%3}, [%4];"
                 : "=r"(r0), "=r"(r1), "=r"(r2), "=r"(r3) : "r"(addr));
}
__device__ __forceinline__ void cp16(uint32_t dst, const void* src) {
    asm volatile("cp.async.cg.shared.global [%0], [%1], 16;" :: "r"(dst), "l"(src));
}
__device__ __forceinline__ void cp_commit() { asm volatile("cp.async.commit_group;"); }
template <int NN> __device__ __forceinline__ void cp_wait() {
    asm volatile("cp.async.wait_group %0;" :: "n"(NN));
}
__device__ __forceinline__ uint32_t pack2h(float a, float b) {
    __half2 h = __floats2half2_rn(a, b);
    return *(uint32_t*)&h;
}

// ---------------- one-time conversions ----------------
__global__ void xconv_kernel(const float* __restrict__ x) {
    size_t i = (size_t)blockIdx.x * blockDim.x + threadIdx.x;
    float4 v = ((const float4*)x)[i];
    uint2 o;
    o.x = pack2h(v.x, v.y);
    o.y = pack2h(v.z, v.w);
    ((uint2*)g_x16)[i] = o;
}
__global__ void wconv_ih_kernel(const float* __restrict__ Wf,
                                const float* __restrict__ Wb,
                                const float* __restrict__ Wc) {
    size_t i = (size_t)blockIdx.x * blockDim.x + threadIdx.x;
    const float* src;
    size_t off;
    if (i < (1u << 20))      { src = Wf; off = i; }
    else if (i < (2u << 20)) { src = Wb; off = i - (1u << 20); }
    else                     { src = Wc; off = i - (2u << 20); }
    float4 v = ((const float4*)src)[off];
    uint2 o;
    o.x = pack2h(v.x, v.y);
    o.y = pack2h(v.z, v.w);
    ((uint2*)g_Wih16)[i] = o;
}

// ---------------- one-time W_hh fragment swizzles (fp16) ----------------
__global__ void wswz_bi_kernel(const float* __restrict__ Wf,
                               const float* __restrict__ Wb) {
    size_t idx = (size_t)blockIdx.x * blockDim.x + threadIdx.x;
    unsigned region = idx >> 15;
    unsigned w = idx & 32767;
    int dir = region >> 6, ublk = region & 63;
    int k16 = w >> 9;
    int jn = (w >> 6) & 7;
    int lane = (w >> 1) & 31;
    int r = w & 1;
    int gid = lane >> 2, tig = lane & 3;
    int col = jn * 8 + gid;
    int gate = col >> 4, u = col & 15;
    int row = gate * N_ + ublk * 16 + u;
    int k = k16 * 16 + r * 8 + tig * 2;
    const float* W = dir ? Wb : Wf;
    g_Wsw_bi[idx] = pack2h(W[(size_t)row * N_ + k], W[(size_t)row * N_ + k + 1]);
}
__global__ void wswz_cell_kernel(const float* __restrict__ Wc) {
    size_t idx = (size_t)blockIdx.x * blockDim.x + threadIdx.x;
    unsigned blk = idx >> 14;
    unsigned w = idx & 16383;
    int k16 = w >> 8;
    int nwq = (w >> 6) & 3;
    int lane = (w >> 1) & 31;
    int r = w & 1;
    int gid = lane >> 2, tig = lane & 3;
    int col = nwq * 8 + gid;
    int gate = col >> 3, u = col & 7;
    int row = gate * N_ + blk * 8 + u;
    int k = k16 * 16 + r * 8 + tig * 2;
    g_Wsw_c[idx] = pack2h(Wc[(size_t)row * N_ + k], Wc[(size_t)row * N_ + k + 1]);
}

// ---------------- fp16 GEMM: 128x128x32, cp.async double buffered, ldmatrix ----------------
__global__ __launch_bounds__(256, 2) void gemm_f16_kernel(
    const __half* __restrict__ A,
    const __half* __restrict__ Wt,
    const float* __restrict__ bias,
    int K, int a_mode, int dst_sel)
{
    float* C = (dst_sel == 0) ? g_Pf : (dst_sel == 1) ? g_Pb : g_Pc;

    __shared__ __align__(16) uint32_t As[2][128 * 20];
    __shared__ __align__(16) uint32_t Ws[2][128 * 20];

    const int tid = threadIdx.x;
    const int m0 = blockIdx.y * 128;
    const int g0 = blockIdx.x * 128;

    const __half* asrc[2];
    const __half* wsrc[2];
    int lrow[2], lseg[2];
#pragma unroll
    for (int i = 0; i < 2; i++) {
        int idx = tid + 256 * i;
        int row = idx >> 2;
        int seg = idx & 3;
        int m = m0 + row;
        int prow = (a_mode == 1) ? ((m & 63) * T_ + (m >> 6)) : m;
        asrc[i] = A + (size_t)prow * K + seg * 8;
        wsrc[i] = Wt + (size_t)(g0 + row) * K + seg * 8;
        lrow[i] = row; lseg[i] = seg;
    }
    uint32_t asm_a[2][2], wsm_a[2][2];
#pragma unroll
    for (int b = 0; b < 2; b++)
#pragma unroll
        for (int i = 0; i < 2; i++) {
            asm_a[b][i] = (uint32_t)__cvta_generic_to_shared(&As[b][lrow[i] * 20 + lseg[i] * 4]);
            wsm_a[b][i] = (uint32_t)__cvta_generic_to_shared(&Ws[b][lrow[i] * 20 + lseg[i] * 4]);
        }

    const int lane = tid & 31;
    const int wid = tid >> 5;
    const int gid = lane >> 2;
    const int tig = lane & 3;
    const int wm = (wid & 3) * 32;
    const int wn = (wid >> 2) * 64;

    const int rowA = lane & 15;
    const int koffA = (lane >> 4) * 4;
    const int cB = (lane & 7) + ((lane >> 4) << 3);
    const int kB = ((lane >> 3) & 1) * 4;

    uint32_t aaddr[2][2], baddr[2][4];
#pragma unroll
    for (int b = 0; b < 2; b++) {
#pragma unroll
        for (int mf = 0; mf < 2; mf++)
            aaddr[b][mf] = (uint32_t)__cvta_generic_to_shared(
                &As[b][(wm + mf * 16 + rowA) * 20 + koffA]);
#pragma unroll
        for (int np = 0; np < 4; np++)
            baddr[b][np] = (uint32_t)__cvta_generic_to_shared(
                &Ws[b][(wn + np * 16 + cB) * 20 + kB]);
    }

    float acc[2][8][4];
#pragma unroll
    for (int mf = 0; mf < 2; mf++)
#pragma unroll
        for (int nf = 0; nf < 8; nf++)
#pragma unroll
            for (int j = 0; j < 4; j++) acc[mf][nf][j] = 0.0f;

    const int NC = K / 32;
#pragma unroll
    for (int i = 0; i < 2; i++) {
        cp16(asm_a[0][i], asrc[i]);
        cp16(wsm_a[0][i], wsrc[i]);
    }
    cp_commit();

    for (int ch = 0; ch < NC; ch++) {
        const int buf = ch & 1;
        if (ch + 1 < NC) {
            const int nb = (ch + 1) & 1;
            const int k0 = (ch + 1) * 32;
#pragma unroll
            for (int i = 0; i < 2; i++) {
                cp16(asm_a[nb][i], asrc[i] + k0);
                cp16(wsm_a[nb][i], wsrc[i] + k0);
            }
            cp_commit();
            cp_wait<1>();
        } else {
            cp_wait<0>();
        }
        __syncthreads();

#pragma unroll
        for (int ks = 0; ks < 2; ks++) {
            const int kbb = ks * 32;
            uint32_t af[2][4];
#pragma unroll
            for (int mf = 0; mf < 2; mf++)
                ldsm_x4(af[mf][0], af[mf][1], af[mf][2], af[mf][3], aaddr[buf][mf] + kbb);
            uint32_t bf[8][2];
#pragma unroll
            for (int np = 0; np < 4; np++)
                ldsm_x4(bf[2 * np][0], bf[2 * np][1], bf[2 * np + 1][0], bf[2 * np + 1][1],
                        baddr[buf][np] + kbb);
#pragma unroll
            for (int mf = 0; mf < 2; mf++)
#pragma unroll
                for (int nf = 0; nf < 8; nf++)
                    mma_f16(acc[mf][nf], af[mf], bf[nf]);
        }
        __syncthreads();
    }

#pragma unroll
    for (int mf = 0; mf < 2; mf++) {
#pragma unroll
        for (int nf = 0; nf < 8; nf++) {
            int row = m0 + wm + mf * 16 + gid;
            int col = g0 + wn + nf * 8 + 2 * tig;
            float b0 = bias[col], b1 = bias[col + 1];
            float2 v0 = make_float2(acc[mf][nf][0] + b0, acc[mf][nf][1] + b1);
            float2 v1 = make_float2(acc[mf][nf][2] + b0, acc[mf][nf][3] + b1);
            *(float2*)&C[(size_t)row * G_ + col] = v0;
            *(float2*)&C[(size_t)(row + 8) * G_ + col] = v1;
        }
    }
}

// ---------------- persistent bilstm recurrence (fp16, W smem-persistent) ----------------
// smem: wsm[32768] | hs0[64*SPH] | hs1[64*SPH] | gates[64*68 floats]
__global__ __launch_bounds__(512, 1) void bilstm_mma_kernel()
{
    extern __shared__ uint32_t smem_u[];
    uint32_t* wsm = smem_u;
    uint32_t* hs[2] = { smem_u + 32768, smem_u + 32768 + 64 * SPH };
    float* gates = (float*)(smem_u + 32768 + 2 * 64 * SPH);

    const int bid = blockIdx.x;
    const int dir = bid >> 6;
    const int u0 = (bid & 63) * 16;
    const float* Pbase = dir ? g_Pb : g_Pf;
    float* c = g_c[dir];

    const int tid = threadIdx.x;
    const int lane = tid & 31;
    const int wid = tid >> 5;
    const int gid = lane >> 2;
    const int tig = lane & 3;
    const int wm = (wid & 1) * 32;
    const int jn = wid >> 1;
    const int wn = jn * 8;

    // one-time: load this block's W region into smem (32768 u32 = 128 KB)
    {
        const uint4* wr = (const uint4*)(g_Wsw_bi + ((size_t)(dir * 64 + (bid & 63)) << 15));
#pragma unroll
        for (int i = 0; i < 16; i++)
            ((uint4*)wsm)[tid + 512 * i] = wr[tid + 512 * i];
    }
    __syncthreads();
    const uint32_t* wq = wsm + jn * 64 + lane * 2;   // + k16*512

    const int r0 = tid >> 4;
    const int seg = tid & 15;
    uint32_t hs_a[2][2];
#pragma unroll
    for (int b = 0; b < 2; b++) {
        hs_a[b][0] = (uint32_t)__cvta_generic_to_shared(hs[b]) + (r0 * SPH + seg * 4) * 4;
        hs_a[b][1] = (uint32_t)__cvta_generic_to_shared(hs[b]) + ((r0 + 32) * SPH + seg * 4) * 4;
    }

    const int rowA = lane & 15;
    const int koffA = (lane >> 4) * 4;
    uint32_t haddr[2][2];
#pragma unroll
    for (int b = 0; b < 2; b++)
#pragma unroll
        for (int mf = 0; mf < 2; mf++)
            haddr[b][mf] = (uint32_t)__cvta_generic_to_shared(
                &hs[b][(wm + mf * 16 + rowA) * SPH + koffA]);

    for (int s = 0; s < T_; s++) {
        const int t = dir ? (T_ - 1 - s) : s;
        const float* P = Pbase + (size_t)t * B_ * G_;
        const __half* h_prev = g_h16[2 * dir + (s & 1)];
        __half* h_next = g_h16[2 * dir + ((s + 1) & 1)];
        __half* hist = g_bi16 + (size_t)t * B_ * 2 * N_ + dir * N_;

        cp16(hs_a[0][0], h_prev + (size_t)r0 * N_ + seg * 8);
        cp16(hs_a[0][1], h_prev + (size_t)(r0 + 32) * N_ + seg * 8);
        cp_commit();

        float acc[2][4];
#pragma unroll
        for (int mf = 0; mf < 2; mf++)
#pragma unroll
            for (int j = 0; j < 4; j++) acc[mf][j] = 0.0f;

        for (int ch = 0; ch < 8; ch++) {
            const int buf = ch & 1;
            if (ch + 1 < 8) {
                int ko = (ch + 1) * 128;
                cp16(hs_a[buf ^ 1][0], h_prev + (size_t)r0 * N_ + ko + seg * 8);
                cp16(hs_a[buf ^ 1][1], h_prev + (size_t)(r0 + 32) * N_ + ko + seg * 8);
                cp_commit();
                cp_wait<1>();
            } else {
                cp_wait<0>();
            }
            __syncthreads();

#pragma unroll
            for (int l = 0; l < 8; l++) {
                uint32_t af[2][4];
#pragma unroll
                for (int mf = 0; mf < 2; mf++)
                    ldsm_x4(af[mf][0], af[mf][1], af[mf][2], af[mf][3],
                            haddr[buf][mf] + l * 32);
                uint2 wv = *(const uint2*)(wq + (ch * 8 + l) * 512);
                uint32_t bf[2] = { wv.x, wv.y };
#pragma unroll
                for (int mf = 0; mf < 2; mf++)
                    mma_f16(acc[mf], af[mf], bf);
            }
            __syncthreads();
        }

#pragma unroll
        for (int mf = 0; mf < 2; mf++) {
            int row = wm + mf * 16 + gid;
            int col = wn + 2 * tig;
            gates[row * 68 + col]           = acc[mf][0];
            gates[row * 68 + col + 1]       = acc[mf][1];
            gates[(row + 8) * 68 + col]     = acc[mf][2];
            gates[(row + 8) * 68 + col + 1] = acc[mf][3];
        }
        __syncthreads();

#pragma unroll
        for (int i = 0; i < 2; i++) {
            int p = tid + 512 * i;
            int bl = p >> 4;
            int u = p & 15;
            int ug = u0 + u;
            const float* Pb = P + (size_t)bl * G_;
            float ig = gates[bl * 68 + u]      + Pb[ug];
            float fg = gates[bl * 68 + 16 + u] + Pb[N_ + ug];
            float gg = gates[bl * 68 + 32 + u] + Pb[2 * N_ + ug];
            float og = gates[bl * 68 + 48 + u] + Pb[3 * N_ + ug];
            ig = 1.0f / (1.0f + expf(-ig));
            fg = 1.0f / (1.0f + expf(-fg));
            gg = tanhf(gg);
            og = 1.0f / (1.0f + expf(-og));
            size_t ci = (size_t)bl * N_ + ug;
            float cn = fg * c[ci] + ig * gg;
            c[ci] = cn;
            __half hn = __float2half_rn(og * tanhf(cn));
            h_next[ci] = hn;
            hist[(size_t)bl * 2 * N_ + ug] = hn;
        }
        grid_barrier(0, 128);
    }
}

// ---------------- persistent cell recurrence (fp16, W smem-persistent) ----------------
// smem: wsm[16384] | hs[2 buf][2 half][64*SPH] | gates0/1[64*36 floats]
__global__ __launch_bounds__(512, 1) void cell_mma_kernel(float* __restrict__ out)
{
    extern __shared__ uint32_t smem_u[];
    uint32_t* wsm = smem_u;
    uint32_t* hbase = smem_u + 16384;
    uint32_t* hsb[2][2] = {
        { hbase,                hbase + 64 * SPH },
        { hbase + 2 * 64 * SPH, hbase + 3 * 64 * SPH }
    };
    float* gates0 = (float*)(hbase + 4 * 64 * SPH);
    float* gates1 = gates0 + 64 * 36;

    const int bid = blockIdx.x;
    const int u0 = bid * 8;
    float* c = g_c[2];

    const int tid = threadIdx.x;
    const int lane = tid & 31;
    const int wid = tid >> 5;
    const int gid = lane >> 2;
    const int tig = lane & 3;
    const int kh = wid >> 3;
    const int w8 = wid & 7;
    const int wm = (w8 & 1) * 32;
    const int nwq = w8 >> 1;
    const int wn = nwq * 8;

    // one-time: load W region (16384 u32 = 64 KB)
    {
        const uint4* wr = (const uint4*)(g_Wsw_c + ((size_t)bid << 14));
#pragma unroll
        for (int i = 0; i < 8; i++)
            ((uint4*)wsm)[tid + 512 * i] = wr[tid + 512 * i];
    }
    __syncthreads();
    const uint32_t* wq = wsm + nwq * 64 + lane * 2;   // + k16*256
    const int k16base = kh * 32;

    const int r0 = tid >> 4;
    const int seg = tid & 15;
    uint32_t hs_a[2][2][2];
#pragma unroll
    for (int b = 0; b < 2; b++)
#pragma unroll
        for (int hh = 0; hh < 2; hh++) {
            hs_a[b][hh][0] = (uint32_t)__cvta_generic_to_shared(hsb[b][hh]) + (r0 * SPH + seg * 4) * 4;
            hs_a[b][hh][1] = (uint32_t)__cvta_generic_to_shared(hsb[b][hh]) + ((r0 + 32) * SPH + seg * 4) * 4;
        }

    const int rowA = lane & 15;
    const int koffA = (lane >> 4) * 4;
    uint32_t haddr[2][2];
#pragma unroll
    for (int b = 0; b < 2; b++)
#pragma unroll
        for (int mf = 0; mf < 2; mf++)
            haddr[b][mf] = (uint32_t)__cvta_generic_to_shared(
                &hsb[b][kh][(wm + mf * 16 + rowA) * SPH + koffA]);

    for (int s = 0; s < T_; s++) {
        const float* P = g_Pc + (size_t)s * B_ * G_;
        const __half* h_prev = g_h16[4 + (s & 1)];
        __half* h_next = g_h16[4 + ((s + 1) & 1)];

#pragma unroll
        for (int hh = 0; hh < 2; hh++) {
            cp16(hs_a[0][hh][0], h_prev + (size_t)r0 * N_ + hh * 512 + seg * 8);
            cp16(hs_a[0][hh][1], h_prev + (size_t)(r0 + 32) * N_ + hh * 512 + seg * 8);
        }
        cp_commit();

        float acc[2][4];
#pragma unroll
        for (int mf = 0; mf < 2; mf++)
#pragma unroll
            for (int j = 0; j < 4; j++) acc[mf][j] = 0.0f;

        for (int ch = 0; ch < 4; ch++) {
            const int buf = ch & 1;
            if (ch + 1 < 4) {
                int ko = (ch + 1) * 128;
#pragma unroll
                for (int hh = 0; hh < 2; hh++) {
                    cp16(hs_a[buf ^ 1][hh][0], h_prev + (size_t)r0 * N_ + hh * 512 + ko + seg * 8);
                    cp16(hs_a[buf ^ 1][hh][1], h_prev + (size_t)(r0 + 32) * N_ + hh * 512 + ko + seg * 8);
                }
                cp_commit();
                cp_wait<1>();
            } else {
                cp_wait<0>();
            }
            __syncthreads();

#pragma unroll
            for (int l = 0; l < 8; l++) {
                uint32_t af[2][4];
#pragma unroll
                for (int mf = 0; mf < 2; mf++)
                    ldsm_x4(af[mf][0], af[mf][1], af[mf][2], af[mf][3],
                            haddr[buf][mf] + l * 32);
                uint2 wv = *(const uint2*)(wq + (k16base + ch * 8 + l) * 256);
                uint32_t bf[2] = { wv.x, wv.y };
#pragma unroll
                for (int mf = 0; mf < 2; mf++)
                    mma_f16(acc[mf], af[mf], bf);
            }
            __syncthreads();
        }

        float* G = kh ? gates1 : gates0;
#pragma unroll
        for (int mf = 0; mf < 2; mf++) {
            int row = wm + mf * 16 + gid;
            int col = wn + 2 * tig;
            G[row * 36 + col]           = acc[mf][0];
            G[row * 36 + col + 1]       = acc[mf][1];
            G[(row + 8) * 36 + col]     = acc[mf][2];
            G[(row + 8) * 36 + col + 1] = acc[mf][3];
        }
        __syncthreads();

        {
            int bl = tid >> 3;
            int u = tid & 7;
            int ug = u0 + u;
            const float* Pb = P + (size_t)bl * G_;
            float ig = gates0[bl * 36 + u]      + gates1[bl * 36 + u]      + Pb[ug];
            float fg = gates0[bl * 36 + 8 + u]  + gates1[bl * 36 + 8 + u]  + Pb[N_ + ug];
            float gg = gates0[bl * 36 + 16 + u] + gates1[bl * 36 + 16 + u] + Pb[2 * N_ + ug];
            float og = gates0[bl * 36 + 24 + u] + gates1[bl * 36 + 24 + u] + Pb[3 * N_ + ug];
            ig = 1.0f / (1.0f + expf(-ig));
            fg = 1.0f / (1.0f + expf(-fg));
            gg = tanhf(gg);
            og = 1.0f / (1.0f + expf(-og));
            size_t ci = (size_t)bl * N_ + ug;
            float cn = fg * c[ci] + ig * gg;
            c[ci] = cn;
            float hn = og * tanhf(cn);
            out[((size_t)bl * T_ + s) * N_ + ug] = hn;
            h_next[ci] = __float2half_rn(hn);
            if (s == T_ - 1) {
                const size_t tail = (size_t)B_ * T_ * N_;
                out[tail + ci] = hn;
                out[tail + (size_t)B_ * N_ + ci] = cn;
            }
        }
        grid_barrier(1, 128);
    }
}

// ---------------- host launcher ----------------
extern "C" void kernel_launch(void* const* d_in, const int* in_sizes, int n_in,
                              void* d_out, int out_size) {
    (void)in_sizes; (void)n_in; (void)out_size;
    const float* x     = (const float*)d_in[0];
    const float* Wf_ih = (const float*)d_in[1];
    const float* Wf_hh = (const float*)d_in[2];
    const float* bf    = (const float*)d_in[3];
    const float* Wb_ih = (const float*)d_in[4];
    const float* Wb_hh = (const float*)d_in[5];
    const float* bb    = (const float*)d_in[6];
    const float* Wc_ih = (const float*)d_in[7];
    const float* Wc_hh = (const float*)d_in[8];
    const float* bc    = (const float*)d_in[9];
    float* out = (float*)d_out;

    __half *wih, *x16, *bi16;
    cudaGetSymbolAddress((void**)&wih, g_Wih16);
    cudaGetSymbolAddress((void**)&x16, g_x16);
    cudaGetSymbolAddress((void**)&bi16, g_bi16);
    const __half* wih_f = wih;
    const __half* wih_b = wih + (4u << 20);
    const __half* wih_c = wih + (8u << 20);

    const int bilstm_smem = (32768 + 2 * 64 * SPH + 64 * 68) * 4;            // 183296
    const int cell_smem   = (16384 + 4 * 64 * SPH + 2 * 64 * 36) * 4;        // 153600
    cudaFuncSetAttribute(bilstm_mma_kernel, cudaFuncAttributeMaxDynamicSharedMemorySize, bilstm_smem);
    cudaFuncSetAttribute(cell_mma_kernel, cudaFuncAttributeMaxDynamicSharedMemorySize, cell_smem);

    // 1) init + one-time conversions/swizzles
    zero_state_kernel<<<(3 * B_ * N_ + 511) / 512, 512>>>();
    xconv_kernel<<<(8 << 20) / 256, 256>>>(x);
    wconv_ih_kernel<<<(4 << 20) / 256, 256>>>(Wf_ih, Wb_ih, Wc_ih);
    wswz_bi_kernel<<<(4 << 20) / 256, 256>>>(Wf_hh, Wb_hh);
    wswz_cell_kernel<<<(2 << 20) / 256, 256>>>(Wc_hh);

    // 2) input projections (fp16 mma)
    dim3 ggrid(G_ / 128, (T_ * B_) / 128);
    gemm_f16_kernel<<<ggrid, 256>>>(x16, wih_f, bf, N_, 1, 0);
    gemm_f16_kernel<<<ggrid, 256>>>(x16, wih_b, bb, N_, 1, 1);

    // 3) bilstm recurrence
    bilstm_mma_kernel<<<128, 512, bilstm_smem>>>();

    // 4) cell input projection (K = 2N, A = g_bi16)
    gemm_f16_kernel<<<ggrid, 256>>>(bi16, wih_c, bc, 2 * N_, 0, 2);

    // 5) cell recurrence + output (+ hT/cT tail at final step)
    cell_mma_kernel<<<128, 512, cell_smem>>>(out);
}

// round 9
// speedup vs baseline: 1.0248x; 1.0248x over previous
#include <cuda_runtime.h>
#include <cuda_fp16.h>
#include <cstdint>
#include <math.h>

#define T_ 512
#define B_ 64
#define N_ 1024
#define G_ 4096   // 4*N
#define SPF 516   // smem pitch (u32) for a FULL fp16 h row (512 u32 + 4 pad; 516%32==4)

// ---------------- static device scratch ----------------
__device__ float g_Pf[(size_t)T_ * B_ * G_];
__device__ float g_Pb[(size_t)T_ * B_ * G_];
__device__ float g_Pc[(size_t)T_ * B_ * G_];
__device__ __half g_bi16[(size_t)T_ * B_ * 2 * N_];   // bilstm output, fp16
__device__ __half g_x16[(size_t)B_ * T_ * N_];        // inputs converted to fp16
__device__ __half g_Wih16[16 * 1024 * 1024];          // fp16 W_ih: f(4M) b(4M) c(8M)
__device__ __half g_h16[6][B_ * N_];                  // fp16 recurrent h
__device__ float  g_c[3][B_ * N_];                    // fp32 cell state
__device__ uint32_t g_Wsw_bi[2 * 64 * 32768];         // fp16 frag-swizzled W_hh fwd/bwd
__device__ uint32_t g_Wsw_c[128 * 16384];             // fp16 frag-swizzled W_hh cell

__device__ unsigned g_barc[2] = {0, 0};
__device__ unsigned g_barg[2] = {0, 0};

__device__ __forceinline__ void grid_barrier(int which, unsigned nb) {
    __syncthreads();
    if (threadIdx.x == 0) {
        __threadfence();
        volatile unsigned* gen = &g_barg[which];
        unsigned g = *gen;
        if (atomicAdd(&g_barc[which], 1) == nb - 1) {
            g_barc[which] = 0;
            __threadfence();
            atomicExch((unsigned*)gen, g + 1);
        } else {
            while (*gen == g) { }
            __threadfence();
        }
    }
    __syncthreads();
}

__global__ void zero_state_kernel() {
    int i = blockIdx.x * blockDim.x + threadIdx.x;
    if (i < 6 * B_ * N_ / 2) ((uint32_t*)g_h16)[i] = 0;
    if (i < 3 * B_ * N_) ((float*)g_c)[i] = 0.0f;
}

// ---------------- mma / cp.async / ldmatrix helpers ----------------
__device__ __forceinline__ void mma_f16(float* c, const uint32_t* a, const uint32_t* b) {
    asm volatile(
        "mma.sync.aligned.m16n8k16.row.col.f32.f16.f16.f32 "
        "{%0,%1,%2,%3}, {%4,%5,%6,%7}, {%8,%9}, {%0,%1,%2,%3};"
        : "+f"(c[0]), "+f"(c[1]), "+f"(c[2]), "+f"(c[3])
        : "r"(a[0]), "r"(a[1]), "r"(a[2]), "r"(a[3]), "r"(b[0]), "r"(b[1]));
}
__device__ __forceinline__ void ldsm_x4(uint32_t& r0, uint32_t& r1, uint32_t& r2, uint32_t& r3,
                                        uint32_t addr) {
    asm volatile("ldmatrix.sync.aligned.m8n8.x4.shared.b16 {%0,%1,%2,%3}, [%4];"
                 : "=r"(r0), "=r"(r1), "=r"(r2), "=r"(r3) : "r"(addr));
}
__device__ __forceinline__ void cp16(uint32_t dst, const void* src) {
    asm volatile("cp.async.cg.shared.global [%0], [%1], 16;" :: "r"(dst), "l"(src));
}
__device__ __forceinline__ void cp_commit() { asm volatile("cp.async.commit_group;"); }
template <int NN> __device__ __forceinline__ void cp_wait() {
    asm volatile("cp.async.wait_group %0;" :: "n"(NN));
}
__device__ __forceinline__ uint32_t pack2h(float a, float b) {
    __half2 h = __floats2half2_rn(a, b);
    return *(uint32_t*)&h;
}

// ---------------- one-time conversions ----------------
__global__ void xconv_kernel(const float* __restrict__ x) {
    size_t i = (size_t)blockIdx.x * blockDim.x + threadIdx.x;
    float4 v = ((const float4*)x)[i];
    uint2 o;
    o.x = pack2h(v.x, v.y);
    o.y = pack2h(v.z, v.w);
    ((uint2*)g_x16)[i] = o;
}
__global__ void wconv_ih_kernel(const float* __restrict__ Wf,
                                const float* __restrict__ Wb,
                                const float* __restrict__ Wc) {
    size_t i = (size_t)blockIdx.x * blockDim.x + threadIdx.x;
    const float* src;
    size_t off;
    if (i < (1u << 20))      { src = Wf; off = i; }
    else if (i < (2u << 20)) { src = Wb; off = i - (1u << 20); }
    else                     { src = Wc; off = i - (2u << 20); }
    float4 v = ((const float4*)src)[off];
    uint2 o;
    o.x = pack2h(v.x, v.y);
    o.y = pack2h(v.z, v.w);
    ((uint2*)g_Wih16)[i] = o;
}

// ---------------- one-time W_hh fragment swizzles (fp16) ----------------
__global__ void wswz_bi_kernel(const float* __restrict__ Wf,
                               const float* __restrict__ Wb) {
    size_t idx = (size_t)blockIdx.x * blockDim.x + threadIdx.x;
    unsigned region = idx >> 15;
    unsigned w = idx & 32767;
    int dir = region >> 6, ublk = region & 63;
    int k16 = w >> 9;
    int jn = (w >> 6) & 7;
    int lane = (w >> 1) & 31;
    int r = w & 1;
    int gid = lane >> 2, tig = lane & 3;
    int col = jn * 8 + gid;
    int gate = col >> 4, u = col & 15;
    int row = gate * N_ + ublk * 16 + u;
    int k = k16 * 16 + r * 8 + tig * 2;
    const float* W = dir ? Wb : Wf;
    g_Wsw_bi[idx] = pack2h(W[(size_t)row * N_ + k], W[(size_t)row * N_ + k + 1]);
}
__global__ void wswz_cell_kernel(const float* __restrict__ Wc) {
    size_t idx = (size_t)blockIdx.x * blockDim.x + threadIdx.x;
    unsigned blk = idx >> 14;
    unsigned w = idx & 16383;
    int k16 = w >> 8;
    int nwq = (w >> 6) & 3;
    int lane = (w >> 1) & 31;
    int r = w & 1;
    int gid = lane >> 2, tig = lane & 3;
    int col = nwq * 8 + gid;
    int gate = col >> 3, u = col & 7;
    int row = gate * N_ + blk * 8 + u;
    int k = k16 * 16 + r * 8 + tig * 2;
    g_Wsw_c[idx] = pack2h(Wc[(size_t)row * N_ + k], Wc[(size_t)row * N_ + k + 1]);
}

// ---------------- fp16 GEMM: 128x128x32, cp.async double buffered, ldmatrix ----------------
__global__ __launch_bounds__(256, 2) void gemm_f16_kernel(
    const __half* __restrict__ A,
    const __half* __restrict__ Wt,
    const float* __restrict__ bias,
    int K, int a_mode, int dst_sel)
{
    float* C = (dst_sel == 0) ? g_Pf : (dst_sel == 1) ? g_Pb : g_Pc;

    __shared__ __align__(16) uint32_t As[2][128 * 20];
    __shared__ __align__(16) uint32_t Ws[2][128 * 20];

    const int tid = threadIdx.x;
    const int m0 = blockIdx.y * 128;
    const int g0 = blockIdx.x * 128;

    const __half* asrc[2];
    const __half* wsrc[2];
    int lrow[2], lseg[2];
#pragma unroll
    for (int i = 0; i < 2; i++) {
        int idx = tid + 256 * i;
        int row = idx >> 2;
        int seg = idx & 3;
        int m = m0 + row;
        int prow = (a_mode == 1) ? ((m & 63) * T_ + (m >> 6)) : m;
        asrc[i] = A + (size_t)prow * K + seg * 8;
        wsrc[i] = Wt + (size_t)(g0 + row) * K + seg * 8;
        lrow[i] = row; lseg[i] = seg;
    }
    uint32_t asm_a[2][2], wsm_a[2][2];
#pragma unroll
    for (int b = 0; b < 2; b++)
#pragma unroll
        for (int i = 0; i < 2; i++) {
            asm_a[b][i] = (uint32_t)__cvta_generic_to_shared(&As[b][lrow[i] * 20 + lseg[i] * 4]);
            wsm_a[b][i] = (uint32_t)__cvta_generic_to_shared(&Ws[b][lrow[i] * 20 + lseg[i] * 4]);
        }

    const int lane = tid & 31;
    const int wid = tid >> 5;
    const int gid = lane >> 2;
    const int tig = lane & 3;
    const int wm = (wid & 3) * 32;
    const int wn = (wid >> 2) * 64;

    const int rowA = lane & 15;
    const int koffA = (lane >> 4) * 4;
    const int cB = (lane & 7) + ((lane >> 4) << 3);
    const int kB = ((lane >> 3) & 1) * 4;

    uint32_t aaddr[2][2], baddr[2][4];
#pragma unroll
    for (int b = 0; b < 2; b++) {
#pragma unroll
        for (int mf = 0; mf < 2; mf++)
            aaddr[b][mf] = (uint32_t)__cvta_generic_to_shared(
                &As[b][(wm + mf * 16 + rowA) * 20 + koffA]);
#pragma unroll
        for (int np = 0; np < 4; np++)
            baddr[b][np] = (uint32_t)__cvta_generic_to_shared(
                &Ws[b][(wn + np * 16 + cB) * 20 + kB]);
    }

    float acc[2][8][4];
#pragma unroll
    for (int mf = 0; mf < 2; mf++)
#pragma unroll
        for (int nf = 0; nf < 8; nf++)
#pragma unroll
            for (int j = 0; j < 4; j++) acc[mf][nf][j] = 0.0f;

    const int NC = K / 32;
#pragma unroll
    for (int i = 0; i < 2; i++) {
        cp16(asm_a[0][i], asrc[i]);
        cp16(wsm_a[0][i], wsrc[i]);
    }
    cp_commit();

    for (int ch = 0; ch < NC; ch++) {
        const int buf = ch & 1;
        if (ch + 1 < NC) {
            const int nb = (ch + 1) & 1;
            const int k0 = (ch + 1) * 32;
#pragma unroll
            for (int i = 0; i < 2; i++) {
                cp16(asm_a[nb][i], asrc[i] + k0);
                cp16(wsm_a[nb][i], wsrc[i] + k0);
            }
            cp_commit();
            cp_wait<1>();
        } else {
            cp_wait<0>();
        }
        __syncthreads();

#pragma unroll
        for (int ks = 0; ks < 2; ks++) {
            const int kbb = ks * 32;
            uint32_t af[2][4];
#pragma unroll
            for (int mf = 0; mf < 2; mf++)
                ldsm_x4(af[mf][0], af[mf][1], af[mf][2], af[mf][3], aaddr[buf][mf] + kbb);
            uint32_t bf[8][2];
#pragma unroll
            for (int np = 0; np < 4; np++)
                ldsm_x4(bf[2 * np][0], bf[2 * np][1], bf[2 * np + 1][0], bf[2 * np + 1][1],
                        baddr[buf][np] + kbb);
#pragma unroll
            for (int mf = 0; mf < 2; mf++)
#pragma unroll
                for (int nf = 0; nf < 8; nf++)
                    mma_f16(acc[mf][nf], af[mf], bf[nf]);
        }
        __syncthreads();
    }

#pragma unroll
    for (int mf = 0; mf < 2; mf++) {
#pragma unroll
        for (int nf = 0; nf < 8; nf++) {
            int row = m0 + wm + mf * 16 + gid;
            int col = g0 + wn + nf * 8 + 2 * tig;
            float b0 = bias[col], b1 = bias[col + 1];
            float2 v0 = make_float2(acc[mf][nf][0] + b0, acc[mf][nf][1] + b1);
            float2 v1 = make_float2(acc[mf][nf][2] + b0, acc[mf][nf][3] + b1);
            *(float2*)&C[(size_t)row * G_ + col] = v0;
            *(float2*)&C[(size_t)(row + 8) * G_ + col] = v1;
        }
    }
}

// ---------------- persistent bilstm recurrence (full-h staging, 3 sync phases) ----------------
// smem: hs[64][SPF] | gates[64*68 floats]. W fragments streamed from gmem (uint2 queue).
__global__ __launch_bounds__(512, 1) void bilstm_mma_kernel()
{
    extern __shared__ uint32_t smem_u[];
    uint32_t* hs = smem_u;                         // 64*SPF
    float* gates = (float*)(smem_u + 64 * SPF);    // [64][68]

    const int bid = blockIdx.x;
    const int dir = bid >> 6;
    const int u0 = (bid & 63) * 16;
    const float* Pbase = dir ? g_Pb : g_Pf;
    float* c = g_c[dir];

    const int tid = threadIdx.x;
    const int lane = tid & 31;
    const int wid = tid >> 5;
    const int gid = lane >> 2;
    const int tig = lane & 3;
    const int wm = (wid & 1) * 32;
    const int jn = wid >> 1;
    const int wn = jn * 8;

    const uint32_t* wp = g_Wsw_bi + ((size_t)(dir * 64 + (bid & 63)) << 15)
                       + jn * 64 + lane * 2;       // + k16*512

    // staging: 8 threads per row, 16 segs each
    const int srow = tid >> 3;
    const int sseg = tid & 7;
    const uint32_t hs_row = (uint32_t)__cvta_generic_to_shared(hs) + (uint32_t)srow * SPF * 4;

    // ldmatrix addresses
    const int rowA = lane & 15;
    const int koffA = (lane >> 4) * 4;
    uint32_t haddr[2];
#pragma unroll
    for (int mf = 0; mf < 2; mf++)
        haddr[mf] = (uint32_t)__cvta_generic_to_shared(
            &hs[(wm + mf * 16 + rowA) * SPF + koffA]);

    // activation indices (2 pairs per thread)
    int abl[2], au[2];
#pragma unroll
    for (int i = 0; i < 2; i++) {
        int p = tid + 512 * i;
        abl[i] = p >> 4;
        au[i] = p & 15;
    }

    for (int s = 0; s < T_; s++) {
        const int t = dir ? (T_ - 1 - s) : s;
        const float* P = Pbase + (size_t)t * B_ * G_;
        const __half* h_prev = g_h16[2 * dir + (s & 1)];
        __half* h_next = g_h16[2 * dir + ((s + 1) & 1)];
        __half* hist = g_bi16 + (size_t)t * B_ * 2 * N_ + dir * N_;

        // prefetch P for activation (overlaps with staging + mma)
        float pre[2][4];
#pragma unroll
        for (int i = 0; i < 2; i++) {
            const float* Pb = P + (size_t)abl[i] * G_;
            int ug = u0 + au[i];
            pre[i][0] = Pb[ug];
            pre[i][1] = Pb[N_ + ug];
            pre[i][2] = Pb[2 * N_ + ug];
            pre[i][3] = Pb[3 * N_ + ug];
        }

        // stage full h in two committed halves
        const __half* hp = h_prev + (size_t)srow * N_;
#pragma unroll
        for (int j = 0; j < 8; j++) {
            int seg = sseg + 8 * j;
            cp16(hs_row + seg * 16, hp + seg * 8);
        }
        cp_commit();
#pragma unroll
        for (int j = 8; j < 16; j++) {
            int seg = sseg + 8 * j;
            cp16(hs_row + seg * 16, hp + seg * 8);
        }
        cp_commit();

        // W queue group 0
        uint2 wcur[8], wnext[8];
#pragma unroll
        for (int l = 0; l < 8; l++)
            wcur[l] = *(const uint2*)(wp + (size_t)l * 512);

        float acc[2][4];
#pragma unroll
        for (int mf = 0; mf < 2; mf++)
#pragma unroll
            for (int j = 0; j < 4; j++) acc[mf][j] = 0.0f;

        cp_wait<1>();
        __syncthreads();

#pragma unroll
        for (int gi = 0; gi < 8; gi++) {
            if (gi == 4) {
                cp_wait<0>();
                __syncthreads();
            }
            if (gi < 7) {
#pragma unroll
                for (int l = 0; l < 8; l++)
                    wnext[l] = *(const uint2*)(wp + (size_t)((gi + 1) * 8 + l) * 512);
            }
#pragma unroll
            for (int l = 0; l < 8; l++) {
                const int g16 = gi * 8 + l;
                uint32_t af[2][4];
#pragma unroll
                for (int mf = 0; mf < 2; mf++)
                    ldsm_x4(af[mf][0], af[mf][1], af[mf][2], af[mf][3],
                            haddr[mf] + g16 * 32);
                uint32_t bf[2] = { wcur[l].x, wcur[l].y };
#pragma unroll
                for (int mf = 0; mf < 2; mf++)
                    mma_f16(acc[mf], af[mf], bf);
            }
            if (gi < 7) {
#pragma unroll
                for (int l = 0; l < 8; l++) wcur[l] = wnext[l];
            }
        }
        __syncthreads();   // mma reads done before gates overwrite region? (gates separate; this orders gates writes vs prior activation via barrier) -- keep for staging reuse safety

#pragma unroll
        for (int mf = 0; mf < 2; mf++) {
            int row = wm + mf * 16 + gid;
            int col = wn + 2 * tig;
            gates[row * 68 + col]           = acc[mf][0];
            gates[row * 68 + col + 1]       = acc[mf][1];
            gates[(row + 8) * 68 + col]     = acc[mf][2];
            gates[(row + 8) * 68 + col + 1] = acc[mf][3];
        }
        __syncthreads();

#pragma unroll
        for (int i = 0; i < 2; i++) {
            int bl = abl[i];
            int u = au[i];
            int ug = u0 + u;
            float ig = gates[bl * 68 + u]      + pre[i][0];
            float fg = gates[bl * 68 + 16 + u] + pre[i][1];
            float gg = gates[bl * 68 + 32 + u] + pre[i][2];
            float og = gates[bl * 68 + 48 + u] + pre[i][3];
            ig = 1.0f / (1.0f + expf(-ig));
            fg = 1.0f / (1.0f + expf(-fg));
            gg = tanhf(gg);
            og = 1.0f / (1.0f + expf(-og));
            size_t ci = (size_t)bl * N_ + ug;
            float cn = fg * c[ci] + ig * gg;
            c[ci] = cn;
            __half hn = __float2half_rn(og * tanhf(cn));
            h_next[ci] = hn;
            hist[(size_t)bl * 2 * N_ + ug] = hn;
        }
        grid_barrier(dir, 64);
    }
}

// ---------------- persistent cell recurrence (full-h staging, W smem) ----------------
// smem: wsm[16384] | hs[64][SPF] | gates0/1[64*36 floats]
__global__ __launch_bounds__(512, 1) void cell_mma_kernel(float* __restrict__ out)
{
    extern __shared__ uint32_t smem_u[];
    uint32_t* wsm = smem_u;
    uint32_t* hs = smem_u + 16384;
    float* gates0 = (float*)(hs + 64 * SPF);
    float* gates1 = gates0 + 64 * 36;

    const int bid = blockIdx.x;
    const int u0 = bid * 8;
    float* c = g_c[2];

    const int tid = threadIdx.x;
    const int lane = tid & 31;
    const int wid = tid >> 5;
    const int gid = lane >> 2;
    const int tig = lane & 3;
    const int kh = wid >> 3;
    const int w8 = wid & 7;
    const int wm = (w8 & 1) * 32;
    const int nwq = w8 >> 1;
    const int wn = nwq * 8;

    // one-time: W region to smem (64 KB)
    {
        const uint4* wr = (const uint4*)(g_Wsw_c + ((size_t)bid << 14));
#pragma unroll
        for (int i = 0; i < 8; i++)
            ((uint4*)wsm)[tid + 512 * i] = wr[tid + 512 * i];
    }
    __syncthreads();
    const uint32_t* wq = wsm + nwq * 64 + lane * 2;   // + k16*256
    const int k16base = kh * 32;

    const int srow = tid >> 3;
    const int sseg = tid & 7;
    const uint32_t hs_row = (uint32_t)__cvta_generic_to_shared(hs) + (uint32_t)srow * SPF * 4;

    const int rowA = lane & 15;
    const int koffA = (lane >> 4) * 4;
    uint32_t haddr[2];
#pragma unroll
    for (int mf = 0; mf < 2; mf++)
        haddr[mf] = (uint32_t)__cvta_generic_to_shared(
            &hs[(wm + mf * 16 + rowA) * SPF + kh * 256 + koffA]);

    const int abl = tid >> 3;
    const int au = tid & 7;

    for (int s = 0; s < T_; s++) {
        const float* P = g_Pc + (size_t)s * B_ * G_;
        const __half* h_prev = g_h16[4 + (s & 1)];
        __half* h_next = g_h16[4 + ((s + 1) & 1)];

        // prefetch P
        float pre[4];
        {
            const float* Pb = P + (size_t)abl * G_;
            int ug = u0 + au;
            pre[0] = Pb[ug];
            pre[1] = Pb[N_ + ug];
            pre[2] = Pb[2 * N_ + ug];
            pre[3] = Pb[3 * N_ + ug];
        }

        // stage full h (single phase)
        const __half* hp = h_prev + (size_t)srow * N_;
#pragma unroll
        for (int j = 0; j < 16; j++) {
            int seg = sseg + 8 * j;
            cp16(hs_row + seg * 16, hp + seg * 8);
        }
        cp_commit();

        float acc[2][4];
#pragma unroll
        for (int mf = 0; mf < 2; mf++)
#pragma unroll
            for (int j = 0; j < 4; j++) acc[mf][j] = 0.0f;

        cp_wait<0>();
        __syncthreads();

#pragma unroll
        for (int l = 0; l < 32; l++) {
            uint32_t af[2][4];
#pragma unroll
            for (int mf = 0; mf < 2; mf++)
                ldsm_x4(af[mf][0], af[mf][1], af[mf][2], af[mf][3],
                        haddr[mf] + l * 32);
            uint2 wv = *(const uint2*)(wq + (size_t)(k16base + l) * 256);
            uint32_t bf[2] = { wv.x, wv.y };
#pragma unroll
            for (int mf = 0; mf < 2; mf++)
                mma_f16(acc[mf], af[mf], bf);
        }
        __syncthreads();

        float* G = kh ? gates1 : gates0;
#pragma unroll
        for (int mf = 0; mf < 2; mf++) {
            int row = wm + mf * 16 + gid;
            int col = wn + 2 * tig;
            G[row * 36 + col]           = acc[mf][0];
            G[row * 36 + col + 1]       = acc[mf][1];
            G[(row + 8) * 36 + col]     = acc[mf][2];
            G[(row + 8) * 36 + col + 1] = acc[mf][3];
        }
        __syncthreads();

        {
            int ug = u0 + au;
            float ig = gates0[abl * 36 + au]      + gates1[abl * 36 + au]      + pre[0];
            float fg = gates0[abl * 36 + 8 + au]  + gates1[abl * 36 + 8 + au]  + pre[1];
            float gg = gates0[abl * 36 + 16 + au] + gates1[abl * 36 + 16 + au] + pre[2];
            float og = gates0[abl * 36 + 24 + au] + gates1[abl * 36 + 24 + au] + pre[3];
            ig = 1.0f / (1.0f + expf(-ig));
            fg = 1.0f / (1.0f + expf(-fg));
            gg = tanhf(gg);
            og = 1.0f / (1.0f + expf(-og));
            size_t ci = (size_t)abl * N_ + ug;
            float cn = fg * c[ci] + ig * gg;
            c[ci] = cn;
            float hn = og * tanhf(cn);
            out[((size_t)abl * T_ + s) * N_ + ug] = hn;
            h_next[ci] = __float2half_rn(hn);
            if (s == T_ - 1) {
                const size_t tail = (size_t)B_ * T_ * N_;
                out[tail + ci] = hn;
                out[tail + (size_t)B_ * N_ + ci] = cn;
            }
        }
        grid_barrier(0, 128);
    }
}

// ---------------- host launcher ----------------
extern "C" void kernel_launch(void* const* d_in, const int* in_sizes, int n_in,
                              void* d_out, int out_size) {
    (void)in_sizes; (void)n_in; (void)out_size;
    const float* x     = (const float*)d_in[0];
    const float* Wf_ih = (const float*)d_in[1];
    const float* Wf_hh = (const float*)d_in[2];
    const float* bf    = (const float*)d_in[3];
    const float* Wb_ih = (const float*)d_in[4];
    const float* Wb_hh = (const float*)d_in[5];
    const float* bb    = (const float*)d_in[6];
    const float* Wc_ih = (const float*)d_in[7];
    const float* Wc_hh = (const float*)d_in[8];
    const float* bc    = (const float*)d_in[9];
    float* out = (float*)d_out;

    __half *wih, *x16, *bi16;
    cudaGetSymbolAddress((void**)&wih, g_Wih16);
    cudaGetSymbolAddress((void**)&x16, g_x16);
    cudaGetSymbolAddress((void**)&bi16, g_bi16);
    const __half* wih_f = wih;
    const __half* wih_b = wih + (4u << 20);
    const __half* wih_c = wih + (8u << 20);

    const int bilstm_smem = (64 * SPF + 64 * 68) * 4;                 // 149504
    const int cell_smem   = (16384 + 64 * SPF + 2 * 64 * 36) * 4;     // 216064
    cudaFuncSetAttribute(bilstm_mma_kernel, cudaFuncAttributeMaxDynamicSharedMemorySize, bilstm_smem);
    cudaFuncSetAttribute(cell_mma_kernel, cudaFuncAttributeMaxDynamicSharedMemorySize, cell_smem);

    // 1) init + one-time conversions/swizzles
    zero_state_kernel<<<(3 * B_ * N_ + 511) / 512, 512>>>();
    xconv_kernel<<<(8 << 20) / 256, 256>>>(x);
    wconv_ih_kernel<<<(4 << 20) / 256, 256>>>(Wf_ih, Wb_ih, Wc_ih);
    wswz_bi_kernel<<<(4 << 20) / 256, 256>>>(Wf_hh, Wb_hh);
    wswz_cell_kernel<<<(2 << 20) / 256, 256>>>(Wc_hh);

    // 2) input projections (fp16 mma)
    dim3 ggrid(G_ / 128, (T_ * B_) / 128);
    gemm_f16_kernel<<<ggrid, 256>>>(x16, wih_f, bf, N_, 1, 0);
    gemm_f16_kernel<<<ggrid, 256>>>(x16, wih_b, bb, N_, 1, 1);

    // 3) bilstm recurrence
    bilstm_mma_kernel<<<128, 512, bilstm_smem>>>();

    // 4) cell input projection (K = 2N, A = g_bi16)
    gemm_f16_kernel<<<ggrid, 256>>>(bi16, wih_c, bc, 2 * N_, 0, 2);

    // 5) cell recurrence + output (+ hT/cT tail at final step)
    cell_mma_kernel<<<128, 512, cell_smem>>>(out);
}